// round 12
// baseline (speedup 1.0000x reference)
#include <cuda_runtime.h>
#include <math.h>

#define NN 65536
#define EE 524288
#define NBLK 2
#define NHD 4
#define NCL 4
#define FEAT 64
#define EMB 128
#define OUTD 32
#define GB 256
#define GSZ 256

typedef unsigned long long u64;

// ---------------- scratch (static device globals; no allocation) ----------------
__device__ int g_deg[NN];               // zeroed at end of each run (k_cls) + static init
__device__ int g_off[NN + 1];
__device__ int g_pos[NN];
__device__ int g_csr[EE];
__device__ int g_scanflag[64];          // zeroed at end of each run (k_cls) + static init
__device__ int g_scanincl[64];
__device__ float g_cur[(size_t)NN * EMB];
__device__ float g_new[(size_t)NN * EMB];
__device__ float g_scores[NHD * NN];
__device__ float g_smv[NHD * NN];
__device__ unsigned char g_keepm[NN];
__device__ int g_klist[NHD * NN];
__device__ int g_kcnt[NHD];
__device__ float g_bsum[EMB];           // zeroed at end of each run (k_cls) + static init
__device__ float g_bsumsq[EMB];
__device__ float g_logits[GB * NCL];

__device__ __forceinline__ float lrelu(float v) { return v > 0.f ? v : 0.01f * v; }
__device__ __forceinline__ u64 pk2(float lo, float hi) {
    u64 r; asm("mov.b64 %0, {%1,%2};" : "=l"(r) : "f"(lo), "f"(hi)); return r;
}
__device__ __forceinline__ void upk2(u64 v, float& lo, float& hi) {
    asm("mov.b64 {%0,%1}, %2;" : "=f"(lo), "=f"(hi) : "l"(v));
}
__device__ __forceinline__ u64 ffma2(u64 a, u64 b, u64 c) {
    u64 d; asm("fma.rn.f32x2 %0,%1,%2,%3;" : "=l"(d) : "l"(a), "l"(b), "l"(c)); return d;
}

// shuffle-based block reductions (256 threads, 8 warps, 2 syncs each)
__device__ __forceinline__ float bredmax(float v, float* sh8) {
    int lane = threadIdx.x & 31, w = threadIdx.x >> 5;
#pragma unroll
    for (int o = 16; o; o >>= 1) v = fmaxf(v, __shfl_xor_sync(0xffffffffu, v, o));
    if (lane == 0) sh8[w] = v;
    __syncthreads();
    float m = fmaxf(fmaxf(fmaxf(sh8[0], sh8[1]), fmaxf(sh8[2], sh8[3])),
                    fmaxf(fmaxf(sh8[4], sh8[5]), fmaxf(sh8[6], sh8[7])));
    __syncthreads();
    return m;
}
__device__ __forceinline__ float bredsum(float v, float* sh8) {
    int lane = threadIdx.x & 31, w = threadIdx.x >> 5;
#pragma unroll
    for (int o = 16; o; o >>= 1) v += __shfl_xor_sync(0xffffffffu, v, o);
    if (lane == 0) sh8[w] = v;
    __syncthreads();
    float m = ((sh8[0] + sh8[1]) + (sh8[2] + sh8[3])) + ((sh8[4] + sh8[5]) + (sh8[6] + sh8[7]));
    __syncthreads();
    return m;
}

// ---------------- L1: histogram (2 edges/thread) ----------------
__global__ void k_hist(const int* __restrict__ ei) {
    int e = (blockIdx.x * 256 + threadIdx.x) * 2;
    int2 d2 = *(const int2*)&ei[EE + e];
    atomicAdd(&g_deg[d2.x], 1);
    atomicAdd(&g_deg[d2.y], 1);
}

// ---------------- L2: exclusive scan (warp-shuffle local scan + parallel lookback) ----------------
__global__ void k_scanF() {
    __shared__ int wsum[32];
    __shared__ int red[64];
    __shared__ int s_prev;
    int b = blockIdx.x, t = threadIdx.x;
    int w = t >> 5, l = t & 31;
    int i = b * 1024 + t;
    int v = g_deg[i];
    int s = v;
#pragma unroll
    for (int o = 1; o < 32; o <<= 1) {
        int n = __shfl_up_sync(0xffffffffu, s, o);
        if (l >= o) s += n;
    }
    if (l == 31) wsum[w] = s;
    __syncthreads();
    if (w == 0) {
        int t2 = wsum[l];
        int s2 = t2;
#pragma unroll
        for (int o = 1; o < 32; o <<= 1) {
            int n = __shfl_up_sync(0xffffffffu, s2, o);
            if (l >= o) s2 += n;
        }
        wsum[l] = s2;
    }
    __syncthreads();
    int incl = s + (w > 0 ? wsum[w - 1] : 0);
    int btotal = wsum[31];
    if (t == 0) {
        g_scanincl[b] = btotal;
        __threadfence();
        atomicExch(&g_scanflag[b], 1);
    }
    int pv = 0;
    if (t < b) {
        while (atomicAdd(&g_scanflag[t], 0) == 0) {}
        __threadfence();
        pv = g_scanincl[t];
    }
    if (t < 64) red[t] = pv;
    __syncthreads();
    if (t == 0) {
        int a = 0;
#pragma unroll
        for (int k = 0; k < 64; k++) a += red[k];
        s_prev = a;
    }
    __syncthreads();
    int off = incl - v + s_prev;
    g_off[i] = off;
    g_pos[i] = off;
    if (i == 0) g_off[NN] = EE;
}

// ---------------- L3: scatter to CSR (4 edges/thread, 4 independent chains) ----------------
__global__ void k_scatter(const int* __restrict__ ei) {
    int e = (blockIdx.x * 256 + threadIdx.x) * 4;
    int4 s4 = *(const int4*)&ei[e];
    int4 d4 = *(const int4*)&ei[EE + e];
    int p0 = atomicAdd(&g_pos[d4.x], 1);
    int p1 = atomicAdd(&g_pos[d4.y], 1);
    int p2 = atomicAdd(&g_pos[d4.z], 1);
    int p3 = atomicAdd(&g_pos[d4.w], 1);
    g_csr[p0] = s4.x;
    g_csr[p1] = s4.y;
    g_csr[p2] = s4.z;
    g_csr[p3] = s4.w;
}

// ---------------- L4 (ncu slot): FUSED max-agg + conv0 GEMM (R11-measured, 88.9us) ----------------
__global__ void __launch_bounds__(256) k_conv0F(const float* __restrict__ x,
                                                const float* __restrict__ Wrel,
                                                const float* __restrict__ Wroot,
                                                const float* __restrict__ b0) {
    __shared__ __align__(16) char arena[43008];
    float (*aggS)[64] = reinterpret_cast<float(*)[64]>(arena);
    float (*s_red)[132] = reinterpret_cast<float(*)[132]>(arena);   // aliases aggS (epilogue)
    float (*inT)[76] = reinterpret_cast<float(*)[76]>(arena + 16384);
    float (*Ws)[132] = reinterpret_cast<float(*)[132]>(arena + 26112);

    int tid = threadIdx.x;
    int warp = tid >> 5, lane = tid & 31;
    int rbase = blockIdx.x * 64;

    // ---- phase 1: max-aggregation for this block's 64 rows (float2 gathers) ----
#pragma unroll
    for (int j = 0; j < 8; j++) {
        int node = warp * 8 + j;
        int row = rbase + node;
        int beg = g_off[row], end = g_off[row + 1];
        float2 m = make_float2(-INFINITY, -INFINITY);
        int e = beg;
        for (; e + 4 <= end; e += 4) {
            int s0 = g_csr[e], s1 = g_csr[e + 1], s2 = g_csr[e + 2], s3 = g_csr[e + 3];
            float2 v0 = *(const float2*)&x[s0 * FEAT + lane * 2];
            float2 v1 = *(const float2*)&x[s1 * FEAT + lane * 2];
            float2 v2 = *(const float2*)&x[s2 * FEAT + lane * 2];
            float2 v3 = *(const float2*)&x[s3 * FEAT + lane * 2];
            m.x = fmaxf(fmaxf(m.x, v0.x), fmaxf(fmaxf(v1.x, v2.x), v3.x));
            m.y = fmaxf(fmaxf(m.y, v0.y), fmaxf(fmaxf(v1.y, v2.y), v3.y));
        }
        for (; e < end; e++) {
            int s = g_csr[e];
            float2 v = *(const float2*)&x[s * FEAT + lane * 2];
            m.x = fmaxf(m.x, v.x);
            m.y = fmaxf(m.y, v.y);
        }
        if (beg == end) { m.x = 0.f; m.y = 0.f; }
        *(float2*)&aggS[node][lane * 2] = m;
    }
    __syncthreads();

    // ---- phase 2: GEMM over K=128 (tx=rows/4, ty=cols/8) ----
    int tx = tid & 15, ty = tid >> 4;
    u64 acc2[4][4];
#pragma unroll
    for (int j = 0; j < 4; j++)
#pragma unroll
        for (int c = 0; c < 4; c++) acc2[j][c] = 0ull;

    for (int k0 = 0; k0 < 128; k0 += 32) {
        for (int idx = tid; idx < 32 * 64; idx += 256) {
            int r = idx >> 5, kk = idx & 31;
            int kg = k0 + kk;
            float v = (kg < 64) ? aggS[r][kg] : x[(rbase + r) * FEAT + (kg - 64)];
            inT[kk][r] = v;
        }
        for (int idx = tid; idx < 32 * 128; idx += 256) {
            int o = idx >> 5, kk = idx & 31;
            int kg = k0 + kk;
            float v = (kg < 64) ? Wrel[o * 64 + kg] : Wroot[o * 64 + (kg - 64)];
            Ws[kk][o] = v;
        }
        __syncthreads();
#pragma unroll
        for (int kk = 0; kk < 32; kk++) {
            float4 av4 = *(const float4*)&inT[kk][tx * 4];
            ulonglong2 wA = *(const ulonglong2*)&Ws[kk][ty * 8];
            ulonglong2 wB = *(const ulonglong2*)&Ws[kk][ty * 8 + 4];
            u64 w0 = wA.x, w1 = wA.y, w2 = wB.x, w3 = wB.y;
            u64 a0 = pk2(av4.x, av4.x), a1 = pk2(av4.y, av4.y);
            u64 a2 = pk2(av4.z, av4.z), a3 = pk2(av4.w, av4.w);
            acc2[0][0] = ffma2(a0, w0, acc2[0][0]);
            acc2[0][1] = ffma2(a0, w1, acc2[0][1]);
            acc2[0][2] = ffma2(a0, w2, acc2[0][2]);
            acc2[0][3] = ffma2(a0, w3, acc2[0][3]);
            acc2[1][0] = ffma2(a1, w0, acc2[1][0]);
            acc2[1][1] = ffma2(a1, w1, acc2[1][1]);
            acc2[1][2] = ffma2(a1, w2, acc2[1][2]);
            acc2[1][3] = ffma2(a1, w3, acc2[1][3]);
            acc2[2][0] = ffma2(a2, w0, acc2[2][0]);
            acc2[2][1] = ffma2(a2, w1, acc2[2][1]);
            acc2[2][2] = ffma2(a2, w2, acc2[2][2]);
            acc2[2][3] = ffma2(a2, w3, acc2[2][3]);
            acc2[3][0] = ffma2(a3, w0, acc2[3][0]);
            acc2[3][1] = ffma2(a3, w1, acc2[3][1]);
            acc2[3][2] = ffma2(a3, w2, acc2[3][2]);
            acc2[3][3] = ffma2(a3, w3, acc2[3][3]);
        }
        __syncthreads();
    }

    // ---- epilogue: bias + lrelu + store + BN partial stats ----
    float vals[4][8];
#pragma unroll
    for (int j = 0; j < 4; j++) {
        int row = rbase + tx * 4 + j;
        float2* orow = (float2*)&g_cur[(size_t)row * EMB + ty * 8];
#pragma unroll
        for (int c = 0; c < 4; c++) {
            float lo, hi;
            upk2(acc2[j][c], lo, hi);
            int col = ty * 8 + c * 2;
            float v0 = lrelu(lo + b0[col]);
            float v1 = lrelu(hi + b0[col + 1]);
            vals[j][c * 2] = v0; vals[j][c * 2 + 1] = v1;
            orow[c] = make_float2(v0, v1);
        }
    }
    float psum[8], pssq[8];
#pragma unroll
    for (int c = 0; c < 8; c++) {
        float s = 0.f, q = 0.f;
#pragma unroll
        for (int j = 0; j < 4; j++) { s += vals[j][c]; q += vals[j][c] * vals[j][c]; }
        psum[c] = s; pssq[c] = q;
    }
    __syncthreads();
#pragma unroll
    for (int c = 0; c < 8; c++) s_red[tx][ty * 8 + c] = psum[c];
    __syncthreads();
    if (tid < 128) {
        float s = 0.f;
#pragma unroll
        for (int k = 0; k < 16; k++) s += s_red[k][tid];
        atomicAdd(&g_bsum[tid], s);
    }
    __syncthreads();
#pragma unroll
    for (int c = 0; c < 8; c++) s_red[tx][ty * 8 + c] = pssq[c];
    __syncthreads();
    if (tid < 128) {
        float s = 0.f;
#pragma unroll
        for (int k = 0; k < 16; k++) s += s_red[k][tid];
        atomicAdd(&g_bsumsq[tid], s);
    }
}

// ---------------- fused BN-apply (or residual-update) + 4-head scores (2 rows/warp) ----------------
__global__ void __launch_bounds__(256) k_norm_scores(const float* __restrict__ gg,
                                                     const float* __restrict__ bb,
                                                     const float* __restrict__ w4,
                                                     int mode) {
    __shared__ float ws[512];
    int tid = threadIdx.x;
    ws[tid] = w4[tid];
    ws[tid + 256] = w4[tid + 256];
    if (blockIdx.x == 0 && tid < NHD) g_kcnt[tid] = 0;
    __syncthreads();
    int w = tid >> 5, l = tid & 31;
    int row0 = blockIdx.x * 16 + w * 2;
    int f = l * 4;
    const float inv = 1.0f / 65536.0f;
    float4 cg = *(const float4*)&gg[f];
    float4 cb = *(const float4*)&bb[f];
    float4 s4 = *(const float4*)&g_bsum[f];
    float4 q4 = *(const float4*)&g_bsumsq[f];
    float mu0 = s4.x * inv, mu1 = s4.y * inv, mu2 = s4.z * inv, mu3 = s4.w * inv;
    float r0 = rsqrtf(q4.x * inv - mu0 * mu0 + 1e-5f);
    float r1 = rsqrtf(q4.y * inv - mu1 * mu1 + 1e-5f);
    float r2 = rsqrtf(q4.z * inv - mu2 * mu2 + 1e-5f);
    float r3 = rsqrtf(q4.w * inv - mu3 * mu3 + 1e-5f);
    float outv[2][4];
#pragma unroll
    for (int r = 0; r < 2; r++) {
        int row = row0 + r;
        float4 cv = *(const float4*)&g_cur[(size_t)row * EMB + f];
        float v0, v1, v2, v3;
        if (mode == 0) {
            v0 = cg.x * (cv.x - mu0) * r0 + cb.x;
            v1 = cg.y * (cv.y - mu1) * r1 + cb.y;
            v2 = cg.z * (cv.z - mu2) * r2 + cb.z;
            v3 = cg.w * (cv.w - mu3) * r3 + cb.w;
        } else {
            float4 nv = make_float4(0.f, 0.f, 0.f, 0.f);
            unsigned km = g_keepm[row];
            if ((km >> (l >> 3)) & 1u) nv = *(const float4*)&g_new[(size_t)row * EMB + f];
            float b0v = cg.x * (nv.x - mu0) * r0 + cb.x;
            float b1v = cg.y * (nv.y - mu1) * r1 + cb.y;
            float b2v = cg.z * (nv.z - mu2) * r2 + cb.z;
            float b3v = cg.w * (nv.w - mu3) * r3 + cb.w;
            v0 = 0.5f * (cv.x + 0.5f * b0v);
            v1 = 0.5f * (cv.y + 0.5f * b1v);
            v2 = 0.5f * (cv.z + 0.5f * b2v);
            v3 = 0.5f * (cv.w + 0.5f * b3v);
        }
        *(float4*)&g_cur[(size_t)row * EMB + f] = make_float4(v0, v1, v2, v3);
        outv[r][0] = v0; outv[r][1] = v1; outv[r][2] = v2; outv[r][3] = v3;
    }
    float p[2][NHD];
#pragma unroll
    for (int r = 0; r < 2; r++)
#pragma unroll
        for (int h = 0; h < NHD; h++) {
            const float* wh = &ws[h * EMB + f];
            p[r][h] = outv[r][0] * wh[0] + outv[r][1] * wh[1] +
                      outv[r][2] * wh[2] + outv[r][3] * wh[3];
        }
#pragma unroll
    for (int o = 16; o; o >>= 1) {
#pragma unroll
        for (int r = 0; r < 2; r++)
#pragma unroll
            for (int h = 0; h < NHD; h++)
                p[r][h] += __shfl_down_sync(0xffffffffu, p[r][h], o);
    }
    if (l == 0) {
#pragma unroll
        for (int r = 0; r < 2; r++)
#pragma unroll
            for (int h = 0; h < NHD; h++)
                g_scores[h * NN + row0 + r] = p[r][h];
    }
}

// ---------------- topk pool + keep mask + klist ----------------
__global__ void k_poolkeep(float minscore) {
    __shared__ float sh8[8];
    int t = threadIdx.x;
    int i = blockIdx.x * GSZ + t;
    if (blockIdx.x == 0 && t < 128) { g_bsum[t] = 0.f; g_bsumsq[t] = 0.f; }
    __syncthreads();
    unsigned mask = 0;
#pragma unroll
    for (int h = 0; h < NHD; h++) {
        float s = g_scores[h * NN + i];
        float m = bredmax(s, sh8);
        float e = expf(s - m);
        float sum = bredsum(e, sh8);
        float sm = e / (sum + 1e-16f);
        float smax = 1.0f / (sum + 1e-16f);
        float thr = fminf(smax - 1e-7f, minscore);
        bool k = sm > thr;
        g_smv[h * NN + i] = sm;
        if (k) {
            mask |= 1u << h;
            int p = atomicAdd(&g_kcnt[h], 1);
            g_klist[h * NN + p] = i;
        }
        __syncthreads();
    }
    g_keepm[i] = (unsigned char)mask;
}

// ---------------- per-head GraphConv on kept nodes: CSR-walk aggregation + GEMM ----------------
__global__ void k_headgemm(int bi, const float* __restrict__ Wrel,
                           const float* __restrict__ Wroot, const float* __restrict__ bias) {
    int h = blockIdx.y;
    int cnt = g_kcnt[h];
    __shared__ float As[EMB], xs[EMB], pr[128];
    const float* Wr = Wrel + (size_t)((bi * NHD + h) * OUTD) * EMB;
    const float* Wo = Wroot + (size_t)((bi * NHD + h) * OUTD) * EMB;
    const float* bb = bias + (bi * NHD + h) * OUTD;
    int t = threadIdx.x;
    for (int idx = blockIdx.x; idx < cnt; idx += gridDim.x) {
        int i = g_klist[h * NN + idx];
        float smi = g_smv[h * NN + i];
        // masked max-aggregation via CSR in-edge walk (i is kept; need kept srcs)
        int beg = g_off[i], end = g_off[i + 1];
        float m = -INFINITY;
        bool any = false;
        for (int e = beg; e < end; e++) {
            int s = g_csr[e];
            if ((g_keepm[s] >> h) & 1u) {
                any = true;
                float smv = g_smv[h * NN + s];
                m = fmaxf(m, g_cur[(size_t)s * EMB + t] * smv);
            }
        }
        As[t] = any ? m : 0.f;
        xs[t] = g_cur[(size_t)i * EMB + t] * smi;
        __syncthreads();
        int c = t & 31, q = t >> 5;
        float acc = 0.f;
#pragma unroll 8
        for (int k = q * 32; k < q * 32 + 32; k++)
            acc += As[k] * Wr[c * EMB + k] + xs[k] * Wo[c * EMB + k];
        pr[t] = acc;
        __syncthreads();
        if (t < 32) {
            float o = pr[t] + pr[t + 32] + pr[t + 64] + pr[t + 96] + bb[t];
            o = lrelu(o);
            g_new[(size_t)i * EMB + h * OUTD + t] = o;
            atomicAdd(&g_bsum[h * OUTD + t], o);
            atomicAdd(&g_bsumsq[h * OUTD + t], o * o);
        }
        __syncthreads();
    }
}

// ---------------- classification heads + end-of-run state re-zeroing ----------------
__global__ void k_cls(const float* __restrict__ gW1, const float* __restrict__ gb1,
                      const float* __restrict__ gW2, const float* __restrict__ gb2,
                      const float* __restrict__ fW1, const float* __restrict__ fb1,
                      const float* __restrict__ fW2, const float* __restrict__ fb2) {
    __shared__ float sh8[8];
    __shared__ float sms[256], xsh[EMB], gates[256], pooled[EMB], part[128];
    __shared__ int list[256];
    __shared__ int cnt;
    int g = blockIdx.x, c = blockIdx.y, t = threadIdx.x;
    if (c == 0) g_deg[g * 256 + t] = 0;
    if (g == 0 && c == 0) {
        if (t < 64) g_scanflag[t] = 0;
        if (t < 128) { g_bsum[t] = 0.f; g_bsumsq[t] = 0.f; }
    }
    int i = g * GSZ + t;
    float s = g_scores[c * NN + i];
    float m = bredmax(s, sh8);
    float e = expf(s - m);
    float sum = bredsum(e, sh8);
    float sm = e / (sum + 1e-16f);
    sms[t] = sm;
    float smax = 1.0f / (sum + 1e-16f);
    float thr = fminf(smax - 1e-7f, 0.8f);
    bool keep = sm > thr;
    if (t == 0) cnt = 0;
    __syncthreads();
    if (keep) { int p = atomicAdd(&cnt, 1); list[p] = t; }
    __syncthreads();
    int C = cnt;

    for (int idx = 0; idx < C; idx++) {
        int tt = list[idx];
        int ii = g * GSZ + tt;
        if (t < 128) xsh[t] = g_cur[(size_t)ii * EMB + t] * sms[tt];
        __syncthreads();
        if (t < 128) {
            const float* w = gW1 + ((size_t)c * EMB + t) * EMB;
            float u = gb1[c * EMB + t];
#pragma unroll 8
            for (int k = 0; k < EMB; k++) u += xsh[k] * w[k];
            u = lrelu(u);
            part[t] = u * gW2[c * EMB + t];
        }
        __syncthreads();
        if (t < 64) part[t] += part[t + 64];
        __syncthreads();
        if (t < 32) {
            float v = part[t] + part[t + 32];
#pragma unroll
            for (int o = 16; o; o >>= 1) v += __shfl_down_sync(0xffffffffu, v, o);
            if (t == 0) gates[idx] = v + gb2[c];
        }
        __syncthreads();
    }

    float gv = (t < C) ? gates[t] : -INFINITY;
    float m2 = bredmax(gv, sh8);
    float e2 = (t < C) ? expf(gv - m2) : 0.f;
    float s2 = bredsum(e2, sh8);
    float a = e2 / (s2 + 1e-16f);
    __syncthreads();
    if (t < C) gates[t] = a;
    __syncthreads();

    if (t < 128) {
        float acc = 0.f;
        for (int idx = 0; idx < C; idx++) {
            int tt = list[idx];
            acc += gates[idx] * g_cur[(size_t)(g * GSZ + tt) * EMB + t] * sms[tt];
        }
        pooled[t] = acc;
    }
    __syncthreads();

    if (t < 128) {
        const float* w = fW1 + ((size_t)c * EMB + t) * EMB;
        float u = fb1[c * EMB + t];
#pragma unroll 8
        for (int k = 0; k < EMB; k++) u += pooled[k] * w[k];
        u = lrelu(u);
        part[t] = u * fW2[c * EMB + t];
    }
    __syncthreads();
    if (t < 64) part[t] += part[t + 64];
    __syncthreads();
    if (t < 32) {
        float v = part[t] + part[t + 32];
#pragma unroll
        for (int o = 16; o; o >>= 1) v += __shfl_down_sync(0xffffffffu, v, o);
        if (t == 0) g_logits[g * NCL + c] = v + fb2[c];
    }
}

// ---------------- log_softmax ----------------
__global__ void k_logsm(float* __restrict__ out) {
    int g = threadIdx.x;  // 256
    float l[NCL];
#pragma unroll
    for (int c = 0; c < NCL; c++) l[c] = g_logits[g * NCL + c];
    float m = l[0];
#pragma unroll
    for (int c = 1; c < NCL; c++) m = fmaxf(m, l[c]);
    float s = 0.f;
#pragma unroll
    for (int c = 0; c < NCL; c++) s += expf(l[c] - m);
    float ls = logf(s);
#pragma unroll
    for (int c = 0; c < NCL; c++) out[g * NCL + c] = l[c] - m - ls;
}

// ---------------- launch ----------------
extern "C" void kernel_launch(void* const* d_in, const int* in_sizes, int n_in,
                              void* d_out, int out_size) {
    const float* x = (const float*)d_in[0];
    const int* ei = (const int*)d_in[1];
    const float* W_rel0 = (const float*)d_in[3];
    const float* W_root0 = (const float*)d_in[4];
    const float* b0 = (const float*)d_in[5];
    const float* bn0_g = (const float*)d_in[6];
    const float* bn0_b = (const float*)d_in[7];
    const float* blk_pool_w = (const float*)d_in[8];
    const float* blk_Wrel = (const float*)d_in[9];
    const float* blk_Wroot = (const float*)d_in[10];
    const float* blk_b = (const float*)d_in[11];
    const float* blk_bn_g = (const float*)d_in[12];
    const float* blk_bn_b = (const float*)d_in[13];
    const float* cls_pool_w = (const float*)d_in[14];
    const float* cls_gW1 = (const float*)d_in[15];
    const float* cls_gb1 = (const float*)d_in[16];
    const float* cls_gW2 = (const float*)d_in[17];
    const float* cls_gb2 = (const float*)d_in[18];
    const float* cls_fW1 = (const float*)d_in[19];
    const float* cls_fb1 = (const float*)d_in[20];
    const float* cls_fW2 = (const float*)d_in[21];
    const float* cls_fb2 = (const float*)d_in[22];
    float* out = (float*)d_out;

    k_hist<<<EE / 512, 256>>>(ei);              // 1
    k_scanF<<<64, 1024>>>();                    // 2
    k_scatter<<<EE / 1024, 256>>>(ei);          // 3
    k_conv0F<<<NN / 64, 256>>>(x, W_rel0, W_root0, b0);                   // 4 <- ncu slot
    k_norm_scores<<<NN / 16, 256>>>(bn0_g, bn0_b, blk_pool_w, 0);         // 5

    for (int bi = 0; bi < NBLK; bi++) {
        k_poolkeep<<<GB, 256>>>(0.7f);
        k_headgemm<<<dim3(256, NHD), 128>>>(bi, blk_Wrel, blk_Wroot, blk_b);
        const float* nxt = (bi == 0) ? (blk_pool_w + (size_t)NHD * EMB) : cls_pool_w;
        k_norm_scores<<<NN / 16, 256>>>(blk_bn_g + bi * EMB, blk_bn_b + bi * EMB, nxt, 1);
    }

    k_cls<<<dim3(GB, NCL), 256>>>(cls_gW1, cls_gb1, cls_gW2, cls_gb2,
                                  cls_fW1, cls_fb1, cls_fW2, cls_fb2);
    k_logsm<<<1, 256>>>(out);
}

// round 13
// speedup vs baseline: 1.5108x; 1.5108x over previous
#include <cuda_runtime.h>
#include <math.h>

#define NN 65536
#define EE 524288
#define NBLK 2
#define NHD 4
#define NCL 4
#define FEAT 64
#define EMB 128
#define OUTD 32
#define GB 256
#define GSZ 256

typedef unsigned long long u64;

// ---------------- scratch (static device globals; no allocation) ----------------
__device__ int g_deg[NN];               // zeroed at end of each run (k_cls) + static init
__device__ int g_off[NN + 1];
__device__ int g_pos[NN];
__device__ int g_csr[EE];
__device__ int g_scanflag[64];          // zeroed at end of each run (k_cls) + static init
__device__ int g_scanincl[64];
__device__ float g_cur[(size_t)NN * EMB];
__device__ float g_new[(size_t)NN * EMB];
__device__ float g_scores[NHD * NN];
__device__ float g_smv[NHD * NN];
__device__ unsigned char g_keepm[NN];
__device__ int g_klist[NHD * NN];
__device__ int g_kcnt[NHD];
__device__ float g_bsum[EMB];           // zeroed at end of each run (k_cls) + static init
__device__ float g_bsumsq[EMB];
__device__ float g_logits[GB * NCL];

__device__ __forceinline__ float lrelu(float v) { return v > 0.f ? v : 0.01f * v; }
__device__ __forceinline__ u64 pk2(float lo, float hi) {
    u64 r; asm("mov.b64 %0, {%1,%2};" : "=l"(r) : "f"(lo), "f"(hi)); return r;
}
__device__ __forceinline__ void upk2(u64 v, float& lo, float& hi) {
    asm("mov.b64 {%0,%1}, %2;" : "=f"(lo), "=f"(hi) : "l"(v));
}
__device__ __forceinline__ u64 ffma2(u64 a, u64 b, u64 c) {
    u64 d; asm("fma.rn.f32x2 %0,%1,%2,%3;" : "=l"(d) : "l"(a), "l"(b), "l"(c)); return d;
}

// shuffle-based block reductions (256 threads, 8 warps, 2 syncs each)
__device__ __forceinline__ float bredmax(float v, float* sh8) {
    int lane = threadIdx.x & 31, w = threadIdx.x >> 5;
#pragma unroll
    for (int o = 16; o; o >>= 1) v = fmaxf(v, __shfl_xor_sync(0xffffffffu, v, o));
    if (lane == 0) sh8[w] = v;
    __syncthreads();
    float m = fmaxf(fmaxf(fmaxf(sh8[0], sh8[1]), fmaxf(sh8[2], sh8[3])),
                    fmaxf(fmaxf(sh8[4], sh8[5]), fmaxf(sh8[6], sh8[7])));
    __syncthreads();
    return m;
}
__device__ __forceinline__ float bredsum(float v, float* sh8) {
    int lane = threadIdx.x & 31, w = threadIdx.x >> 5;
#pragma unroll
    for (int o = 16; o; o >>= 1) v += __shfl_xor_sync(0xffffffffu, v, o);
    if (lane == 0) sh8[w] = v;
    __syncthreads();
    float m = ((sh8[0] + sh8[1]) + (sh8[2] + sh8[3])) + ((sh8[4] + sh8[5]) + (sh8[6] + sh8[7]));
    __syncthreads();
    return m;
}

// ---------------- L1: histogram (2 edges/thread) ----------------
__global__ void k_hist(const int* __restrict__ ei) {
    int e = (blockIdx.x * 256 + threadIdx.x) * 2;
    int2 d2 = *(const int2*)&ei[EE + e];
    atomicAdd(&g_deg[d2.x], 1);
    atomicAdd(&g_deg[d2.y], 1);
}

// ---------------- L2: exclusive scan (warp-shuffle local scan + parallel lookback) ----------------
__global__ void k_scanF() {
    __shared__ int wsum[32];
    __shared__ int red[64];
    __shared__ int s_prev;
    int b = blockIdx.x, t = threadIdx.x;
    int w = t >> 5, l = t & 31;
    int i = b * 1024 + t;
    int v = g_deg[i];
    int s = v;
#pragma unroll
    for (int o = 1; o < 32; o <<= 1) {
        int n = __shfl_up_sync(0xffffffffu, s, o);
        if (l >= o) s += n;
    }
    if (l == 31) wsum[w] = s;
    __syncthreads();
    if (w == 0) {
        int t2 = wsum[l];
        int s2 = t2;
#pragma unroll
        for (int o = 1; o < 32; o <<= 1) {
            int n = __shfl_up_sync(0xffffffffu, s2, o);
            if (l >= o) s2 += n;
        }
        wsum[l] = s2;
    }
    __syncthreads();
    int incl = s + (w > 0 ? wsum[w - 1] : 0);
    int btotal = wsum[31];
    if (t == 0) {
        g_scanincl[b] = btotal;
        __threadfence();
        atomicExch(&g_scanflag[b], 1);
    }
    int pv = 0;
    if (t < b) {
        while (atomicAdd(&g_scanflag[t], 0) == 0) {}
        __threadfence();
        pv = g_scanincl[t];
    }
    if (t < 64) red[t] = pv;
    __syncthreads();
    if (t == 0) {
        int a = 0;
#pragma unroll
        for (int k = 0; k < 64; k++) a += red[k];
        s_prev = a;
    }
    __syncthreads();
    int off = incl - v + s_prev;
    g_off[i] = off;
    g_pos[i] = off;
    if (i == 0) g_off[NN] = EE;
}

// ---------------- L3: scatter to CSR (4 edges/thread, 4 independent chains) ----------------
__global__ void k_scatter(const int* __restrict__ ei) {
    int e = (blockIdx.x * 256 + threadIdx.x) * 4;
    int4 s4 = *(const int4*)&ei[e];
    int4 d4 = *(const int4*)&ei[EE + e];
    int p0 = atomicAdd(&g_pos[d4.x], 1);
    int p1 = atomicAdd(&g_pos[d4.y], 1);
    int p2 = atomicAdd(&g_pos[d4.z], 1);
    int p3 = atomicAdd(&g_pos[d4.w], 1);
    g_csr[p0] = s4.x;
    g_csr[p1] = s4.y;
    g_csr[p2] = s4.z;
    g_csr[p3] = s4.w;
}

// ---------------- L4 (ncu slot): FUSED max-agg + conv0 GEMM ----------------
__global__ void __launch_bounds__(256) k_conv0F(const float* __restrict__ x,
                                                const float* __restrict__ Wrel,
                                                const float* __restrict__ Wroot,
                                                const float* __restrict__ b0) {
    __shared__ __align__(16) char arena[43008];
    float (*aggS)[64] = reinterpret_cast<float(*)[64]>(arena);
    float (*s_red)[132] = reinterpret_cast<float(*)[132]>(arena);   // aliases aggS (epilogue)
    float (*inT)[76] = reinterpret_cast<float(*)[76]>(arena + 16384);
    float (*Ws)[132] = reinterpret_cast<float(*)[132]>(arena + 26112);

    int tid = threadIdx.x;
    int warp = tid >> 5, lane = tid & 31;
    int rbase = blockIdx.x * 64;

    // ---- phase 1: max-aggregation for this block's 64 rows (float2 gathers) ----
#pragma unroll
    for (int j = 0; j < 8; j++) {
        int node = warp * 8 + j;
        int row = rbase + node;
        int beg = g_off[row], end = g_off[row + 1];
        float2 m = make_float2(-INFINITY, -INFINITY);
        int e = beg;
        for (; e + 4 <= end; e += 4) {
            int s0 = g_csr[e], s1 = g_csr[e + 1], s2 = g_csr[e + 2], s3 = g_csr[e + 3];
            float2 v0 = *(const float2*)&x[s0 * FEAT + lane * 2];
            float2 v1 = *(const float2*)&x[s1 * FEAT + lane * 2];
            float2 v2 = *(const float2*)&x[s2 * FEAT + lane * 2];
            float2 v3 = *(const float2*)&x[s3 * FEAT + lane * 2];
            m.x = fmaxf(fmaxf(m.x, v0.x), fmaxf(fmaxf(v1.x, v2.x), v3.x));
            m.y = fmaxf(fmaxf(m.y, v0.y), fmaxf(fmaxf(v1.y, v2.y), v3.y));
        }
        for (; e < end; e++) {
            int s = g_csr[e];
            float2 v = *(const float2*)&x[s * FEAT + lane * 2];
            m.x = fmaxf(m.x, v.x);
            m.y = fmaxf(m.y, v.y);
        }
        if (beg == end) { m.x = 0.f; m.y = 0.f; }
        *(float2*)&aggS[node][lane * 2] = m;
    }
    __syncthreads();

    // ---- phase 2: GEMM over K=128 (tx=rows/4, ty=cols/8) ----
    int tx = tid & 15, ty = tid >> 4;
    u64 acc2[4][4];
#pragma unroll
    for (int j = 0; j < 4; j++)
#pragma unroll
        for (int c = 0; c < 4; c++) acc2[j][c] = 0ull;

    for (int k0 = 0; k0 < 128; k0 += 32) {
        for (int idx = tid; idx < 32 * 64; idx += 256) {
            int r = idx >> 5, kk = idx & 31;
            int kg = k0 + kk;
            float v = (kg < 64) ? aggS[r][kg] : x[(rbase + r) * FEAT + (kg - 64)];
            inT[kk][r] = v;
        }
        for (int idx = tid; idx < 32 * 128; idx += 256) {
            int o = idx >> 5, kk = idx & 31;
            int kg = k0 + kk;
            float v = (kg < 64) ? Wrel[o * 64 + kg] : Wroot[o * 64 + (kg - 64)];
            Ws[kk][o] = v;
        }
        __syncthreads();
#pragma unroll
        for (int kk = 0; kk < 32; kk++) {
            float4 av4 = *(const float4*)&inT[kk][tx * 4];
            ulonglong2 wA = *(const ulonglong2*)&Ws[kk][ty * 8];
            ulonglong2 wB = *(const ulonglong2*)&Ws[kk][ty * 8 + 4];
            u64 w0 = wA.x, w1 = wA.y, w2 = wB.x, w3 = wB.y;
            u64 a0 = pk2(av4.x, av4.x), a1 = pk2(av4.y, av4.y);
            u64 a2 = pk2(av4.z, av4.z), a3 = pk2(av4.w, av4.w);
            acc2[0][0] = ffma2(a0, w0, acc2[0][0]);
            acc2[0][1] = ffma2(a0, w1, acc2[0][1]);
            acc2[0][2] = ffma2(a0, w2, acc2[0][2]);
            acc2[0][3] = ffma2(a0, w3, acc2[0][3]);
            acc2[1][0] = ffma2(a1, w0, acc2[1][0]);
            acc2[1][1] = ffma2(a1, w1, acc2[1][1]);
            acc2[1][2] = ffma2(a1, w2, acc2[1][2]);
            acc2[1][3] = ffma2(a1, w3, acc2[1][3]);
            acc2[2][0] = ffma2(a2, w0, acc2[2][0]);
            acc2[2][1] = ffma2(a2, w1, acc2[2][1]);
            acc2[2][2] = ffma2(a2, w2, acc2[2][2]);
            acc2[2][3] = ffma2(a2, w3, acc2[2][3]);
            acc2[3][0] = ffma2(a3, w0, acc2[3][0]);
            acc2[3][1] = ffma2(a3, w1, acc2[3][1]);
            acc2[3][2] = ffma2(a3, w2, acc2[3][2]);
            acc2[3][3] = ffma2(a3, w3, acc2[3][3]);
        }
        __syncthreads();
    }

    // ---- epilogue: bias + lrelu + store + BN partial stats ----
    float vals[4][8];
#pragma unroll
    for (int j = 0; j < 4; j++) {
        int row = rbase + tx * 4 + j;
        float2* orow = (float2*)&g_cur[(size_t)row * EMB + ty * 8];
#pragma unroll
        for (int c = 0; c < 4; c++) {
            float lo, hi;
            upk2(acc2[j][c], lo, hi);
            int col = ty * 8 + c * 2;
            float v0 = lrelu(lo + b0[col]);
            float v1 = lrelu(hi + b0[col + 1]);
            vals[j][c * 2] = v0; vals[j][c * 2 + 1] = v1;
            orow[c] = make_float2(v0, v1);
        }
    }
    float psum[8], pssq[8];
#pragma unroll
    for (int c = 0; c < 8; c++) {
        float s = 0.f, q = 0.f;
#pragma unroll
        for (int j = 0; j < 4; j++) { s += vals[j][c]; q += vals[j][c] * vals[j][c]; }
        psum[c] = s; pssq[c] = q;
    }
    __syncthreads();
#pragma unroll
    for (int c = 0; c < 8; c++) s_red[tx][ty * 8 + c] = psum[c];
    __syncthreads();
    if (tid < 128) {
        float s = 0.f;
#pragma unroll
        for (int k = 0; k < 16; k++) s += s_red[k][tid];
        atomicAdd(&g_bsum[tid], s);
    }
    __syncthreads();
#pragma unroll
    for (int c = 0; c < 8; c++) s_red[tx][ty * 8 + c] = pssq[c];
    __syncthreads();
    if (tid < 128) {
        float s = 0.f;
#pragma unroll
        for (int k = 0; k < 16; k++) s += s_red[k][tid];
        atomicAdd(&g_bsumsq[tid], s);
    }
}

// ---------------- fused BN-apply (or residual-update) + 4-head scores (2 rows/warp) ----------------
__global__ void __launch_bounds__(256) k_norm_scores(const float* __restrict__ gg,
                                                     const float* __restrict__ bb,
                                                     const float* __restrict__ w4,
                                                     int mode) {
    __shared__ float ws[512];
    int tid = threadIdx.x;
    ws[tid] = w4[tid];
    ws[tid + 256] = w4[tid + 256];
    if (blockIdx.x == 0 && tid < NHD) g_kcnt[tid] = 0;
    __syncthreads();
    int w = tid >> 5, l = tid & 31;
    int row0 = blockIdx.x * 16 + w * 2;
    int f = l * 4;
    const float inv = 1.0f / 65536.0f;
    float4 cg = *(const float4*)&gg[f];
    float4 cb = *(const float4*)&bb[f];
    float4 s4 = *(const float4*)&g_bsum[f];
    float4 q4 = *(const float4*)&g_bsumsq[f];
    float mu0 = s4.x * inv, mu1 = s4.y * inv, mu2 = s4.z * inv, mu3 = s4.w * inv;
    float r0 = rsqrtf(q4.x * inv - mu0 * mu0 + 1e-5f);
    float r1 = rsqrtf(q4.y * inv - mu1 * mu1 + 1e-5f);
    float r2 = rsqrtf(q4.z * inv - mu2 * mu2 + 1e-5f);
    float r3 = rsqrtf(q4.w * inv - mu3 * mu3 + 1e-5f);
    float outv[2][4];
#pragma unroll
    for (int r = 0; r < 2; r++) {
        int row = row0 + r;
        float4 cv = *(const float4*)&g_cur[(size_t)row * EMB + f];
        float v0, v1, v2, v3;
        if (mode == 0) {
            v0 = cg.x * (cv.x - mu0) * r0 + cb.x;
            v1 = cg.y * (cv.y - mu1) * r1 + cb.y;
            v2 = cg.z * (cv.z - mu2) * r2 + cb.z;
            v3 = cg.w * (cv.w - mu3) * r3 + cb.w;
        } else {
            float4 nv = make_float4(0.f, 0.f, 0.f, 0.f);
            unsigned km = g_keepm[row];
            if ((km >> (l >> 3)) & 1u) nv = *(const float4*)&g_new[(size_t)row * EMB + f];
            float b0v = cg.x * (nv.x - mu0) * r0 + cb.x;
            float b1v = cg.y * (nv.y - mu1) * r1 + cb.y;
            float b2v = cg.z * (nv.z - mu2) * r2 + cb.z;
            float b3v = cg.w * (nv.w - mu3) * r3 + cb.w;
            v0 = 0.5f * (cv.x + 0.5f * b0v);
            v1 = 0.5f * (cv.y + 0.5f * b1v);
            v2 = 0.5f * (cv.z + 0.5f * b2v);
            v3 = 0.5f * (cv.w + 0.5f * b3v);
        }
        *(float4*)&g_cur[(size_t)row * EMB + f] = make_float4(v0, v1, v2, v3);
        outv[r][0] = v0; outv[r][1] = v1; outv[r][2] = v2; outv[r][3] = v3;
    }
    float p[2][NHD];
#pragma unroll
    for (int r = 0; r < 2; r++)
#pragma unroll
        for (int h = 0; h < NHD; h++) {
            const float* wh = &ws[h * EMB + f];
            p[r][h] = outv[r][0] * wh[0] + outv[r][1] * wh[1] +
                      outv[r][2] * wh[2] + outv[r][3] * wh[3];
        }
#pragma unroll
    for (int o = 16; o; o >>= 1) {
#pragma unroll
        for (int r = 0; r < 2; r++)
#pragma unroll
            for (int h = 0; h < NHD; h++)
                p[r][h] += __shfl_down_sync(0xffffffffu, p[r][h], o);
    }
    if (l == 0) {
#pragma unroll
        for (int r = 0; r < 2; r++)
#pragma unroll
            for (int h = 0; h < NHD; h++)
                g_scores[h * NN + row0 + r] = p[r][h];
    }
}

// ---------------- topk pool + keep mask + klist ----------------
__global__ void k_poolkeep(float minscore) {
    __shared__ float sh8[8];
    int t = threadIdx.x;
    int i = blockIdx.x * GSZ + t;
    if (blockIdx.x == 0 && t < 128) { g_bsum[t] = 0.f; g_bsumsq[t] = 0.f; }
    __syncthreads();
    unsigned mask = 0;
#pragma unroll
    for (int h = 0; h < NHD; h++) {
        float s = g_scores[h * NN + i];
        float m = bredmax(s, sh8);
        float e = expf(s - m);
        float sum = bredsum(e, sh8);
        float sm = e / (sum + 1e-16f);
        float smax = 1.0f / (sum + 1e-16f);
        float thr = fminf(smax - 1e-7f, minscore);
        bool k = sm > thr;
        g_smv[h * NN + i] = sm;
        if (k) {
            mask |= 1u << h;
            int p = atomicAdd(&g_kcnt[h], 1);
            g_klist[h * NN + p] = i;
        }
        __syncthreads();
    }
    g_keepm[i] = (unsigned char)mask;
}

// ---------------- per-head GraphConv on kept nodes: CSR-walk aggregation + GEMM ----------------
__global__ void k_headgemm(int bi, const float* __restrict__ Wrel,
                           const float* __restrict__ Wroot, const float* __restrict__ bias) {
    int h = blockIdx.y;
    int cnt = g_kcnt[h];
    __shared__ float As[EMB], xs[EMB], pr[128];
    const float* Wr = Wrel + (size_t)((bi * NHD + h) * OUTD) * EMB;
    const float* Wo = Wroot + (size_t)((bi * NHD + h) * OUTD) * EMB;
    const float* bb = bias + (bi * NHD + h) * OUTD;
    int t = threadIdx.x;
    for (int idx = blockIdx.x; idx < cnt; idx += gridDim.x) {
        int i = g_klist[h * NN + idx];
        float smi = g_smv[h * NN + i];
        // masked max-aggregation via CSR in-edge walk (i is kept; need kept srcs)
        int beg = g_off[i], end = g_off[i + 1];
        float m = -INFINITY;
        bool any = false;
        for (int e = beg; e < end; e++) {
            int s = g_csr[e];
            if ((g_keepm[s] >> h) & 1u) {
                any = true;
                float smv = g_smv[h * NN + s];
                m = fmaxf(m, g_cur[(size_t)s * EMB + t] * smv);
            }
        }
        As[t] = any ? m : 0.f;
        xs[t] = g_cur[(size_t)i * EMB + t] * smi;
        __syncthreads();
        int c = t & 31, q = t >> 5;
        float acc = 0.f;
#pragma unroll 8
        for (int k = q * 32; k < q * 32 + 32; k++)
            acc += As[k] * Wr[c * EMB + k] + xs[k] * Wo[c * EMB + k];
        pr[t] = acc;
        __syncthreads();
        if (t < 32) {
            float o = pr[t] + pr[t + 32] + pr[t + 64] + pr[t + 96] + bb[t];
            o = lrelu(o);
            g_new[(size_t)i * EMB + h * OUTD + t] = o;
            atomicAdd(&g_bsum[h * OUTD + t], o);
            atomicAdd(&g_bsumsq[h * OUTD + t], o * o);
        }
        __syncthreads();
    }
}

// ---------------- classification heads + end-of-run state re-zeroing ----------------
__global__ void k_cls(const float* __restrict__ gW1, const float* __restrict__ gb1,
                      const float* __restrict__ gW2, const float* __restrict__ gb2,
                      const float* __restrict__ fW1, const float* __restrict__ fb1,
                      const float* __restrict__ fW2, const float* __restrict__ fb2) {
    __shared__ float sh8[8];
    __shared__ float sms[256], xsh[EMB], gates[256], pooled[EMB], part[128];
    __shared__ int list[256];
    __shared__ int cnt;
    int g = blockIdx.x, c = blockIdx.y, t = threadIdx.x;
    if (c == 0) g_deg[g * 256 + t] = 0;
    if (g == 0 && c == 0) {
        if (t < 64) g_scanflag[t] = 0;
        if (t < 128) { g_bsum[t] = 0.f; g_bsumsq[t] = 0.f; }
    }
    int i = g * GSZ + t;
    float s = g_scores[c * NN + i];
    float m = bredmax(s, sh8);
    float e = expf(s - m);
    float sum = bredsum(e, sh8);
    float sm = e / (sum + 1e-16f);
    sms[t] = sm;
    float smax = 1.0f / (sum + 1e-16f);
    float thr = fminf(smax - 1e-7f, 0.8f);
    bool keep = sm > thr;
    if (t == 0) cnt = 0;
    __syncthreads();
    if (keep) { int p = atomicAdd(&cnt, 1); list[p] = t; }
    __syncthreads();
    int C = cnt;

    for (int idx = 0; idx < C; idx++) {
        int tt = list[idx];
        int ii = g * GSZ + tt;
        if (t < 128) xsh[t] = g_cur[(size_t)ii * EMB + t] * sms[tt];
        __syncthreads();
        if (t < 128) {
            const float* w = gW1 + ((size_t)c * EMB + t) * EMB;
            float u = gb1[c * EMB + t];
#pragma unroll 8
            for (int k = 0; k < EMB; k++) u += xsh[k] * w[k];
            u = lrelu(u);
            part[t] = u * gW2[c * EMB + t];
        }
        __syncthreads();
        if (t < 64) part[t] += part[t + 64];
        __syncthreads();
        if (t < 32) {
            float v = part[t] + part[t + 32];
#pragma unroll
            for (int o = 16; o; o >>= 1) v += __shfl_down_sync(0xffffffffu, v, o);
            if (t == 0) gates[idx] = v + gb2[c];
        }
        __syncthreads();
    }

    float gv = (t < C) ? gates[t] : -INFINITY;
    float m2 = bredmax(gv, sh8);
    float e2 = (t < C) ? expf(gv - m2) : 0.f;
    float s2 = bredsum(e2, sh8);
    float a = e2 / (s2 + 1e-16f);
    __syncthreads();
    if (t < C) gates[t] = a;
    __syncthreads();

    if (t < 128) {
        float acc = 0.f;
        for (int idx = 0; idx < C; idx++) {
            int tt = list[idx];
            acc += gates[idx] * g_cur[(size_t)(g * GSZ + tt) * EMB + t] * sms[tt];
        }
        pooled[t] = acc;
    }
    __syncthreads();

    if (t < 128) {
        const float* w = fW1 + ((size_t)c * EMB + t) * EMB;
        float u = fb1[c * EMB + t];
#pragma unroll 8
        for (int k = 0; k < EMB; k++) u += pooled[k] * w[k];
        u = lrelu(u);
        part[t] = u * fW2[c * EMB + t];
    }
    __syncthreads();
    if (t < 64) part[t] += part[t + 64];
    __syncthreads();
    if (t < 32) {
        float v = part[t] + part[t + 32];
#pragma unroll
        for (int o = 16; o; o >>= 1) v += __shfl_down_sync(0xffffffffu, v, o);
        if (t == 0) g_logits[g * NCL + c] = v + fb2[c];
    }
}

// ---------------- log_softmax ----------------
__global__ void k_logsm(float* __restrict__ out) {
    int g = threadIdx.x;  // 256
    float l[NCL];
#pragma unroll
    for (int c = 0; c < NCL; c++) l[c] = g_logits[g * NCL + c];
    float m = l[0];
#pragma unroll
    for (int c = 1; c < NCL; c++) m = fmaxf(m, l[c]);
    float s = 0.f;
#pragma unroll
    for (int c = 0; c < NCL; c++) s += expf(l[c] - m);
    float ls = logf(s);
#pragma unroll
    for (int c = 0; c < NCL; c++) out[g * NCL + c] = l[c] - m - ls;
}

// ---------------- launch ----------------
extern "C" void kernel_launch(void* const* d_in, const int* in_sizes, int n_in,
                              void* d_out, int out_size) {
    const float* x = (const float*)d_in[0];
    const int* ei = (const int*)d_in[1];
    const float* W_rel0 = (const float*)d_in[3];
    const float* W_root0 = (const float*)d_in[4];
    const float* b0 = (const float*)d_in[5];
    const float* bn0_g = (const float*)d_in[6];
    const float* bn0_b = (const float*)d_in[7];
    const float* blk_pool_w = (const float*)d_in[8];
    const float* blk_Wrel = (const float*)d_in[9];
    const float* blk_Wroot = (const float*)d_in[10];
    const float* blk_b = (const float*)d_in[11];
    const float* blk_bn_g = (const float*)d_in[12];
    const float* blk_bn_b = (const float*)d_in[13];
    const float* cls_pool_w = (const float*)d_in[14];
    const float* cls_gW1 = (const float*)d_in[15];
    const float* cls_gb1 = (const float*)d_in[16];
    const float* cls_gW2 = (const float*)d_in[17];
    const float* cls_gb2 = (const float*)d_in[18];
    const float* cls_fW1 = (const float*)d_in[19];
    const float* cls_fb1 = (const float*)d_in[20];
    const float* cls_fW2 = (const float*)d_in[21];
    const float* cls_fb2 = (const float*)d_in[22];
    float* out = (float*)d_out;

    k_hist<<<EE / 512, 256>>>(ei);              // 1
    k_scanF<<<64, 1024>>>();                    // 2
    k_scatter<<<EE / 1024, 256>>>(ei);          // 3
    k_conv0F<<<NN / 64, 256>>>(x, W_rel0, W_root0, b0);                   // 4 <- ncu slot
    k_norm_scores<<<NN / 16, 256>>>(bn0_g, bn0_b, blk_pool_w, 0);         // 5

    for (int bi = 0; bi < NBLK; bi++) {
        k_poolkeep<<<GB, 256>>>(0.7f);
        k_headgemm<<<dim3(256, NHD), 128>>>(bi, blk_Wrel, blk_Wroot, blk_b);
        const float* nxt = (bi == 0) ? (blk_pool_w + (size_t)NHD * EMB) : cls_pool_w;
        k_norm_scores<<<NN / 16, 256>>>(blk_bn_g + bi * EMB, blk_bn_b + bi * EMB, nxt, 1);
    }

    k_cls<<<dim3(GB, NCL), 256>>>(cls_gW1, cls_gb1, cls_gW2, cls_gb2,
                                  cls_fW1, cls_fb1, cls_fW2, cls_fb2);
    k_logsm<<<1, 256>>>(out);
}

// round 16
// speedup vs baseline: 1.6017x; 1.0602x over previous
#include <cuda_runtime.h>
#include <math.h>

#define NN 65536
#define EE 524288
#define NBLK 2
#define NHD 4
#define NCL 4
#define FEAT 64
#define EMB 128
#define OUTD 32
#define GB 256
#define GSZ 256

typedef unsigned long long u64;

// ---------------- scratch (static device globals; no allocation) ----------------
__device__ int g_deg[NN];               // zeroed at end of each run (k_cls) + static init
__device__ int g_off[NN + 1];
__device__ int g_pos[NN];
__device__ int g_csr[EE];
__device__ int g_scanflag[64];          // zeroed at end of each run (k_cls) + static init
__device__ int g_scanincl[64];
__device__ float g_cur[(size_t)NN * EMB];
__device__ float g_new[(size_t)NN * EMB];
__device__ float g_scores[NHD * NN];
__device__ float g_smv[NHD * NN];
__device__ unsigned char g_keepm[NN];
__device__ int g_klist[NHD * NN];
__device__ int g_kcnt[NHD];
__device__ float g_bsum[EMB];           // zeroed at end of each run (k_cls) + static init
__device__ float g_bsumsq[EMB];
__device__ float g_logits[GB * NCL];
__device__ int g_done[GB];              // per-graph completion counters (self-resetting)

__device__ __forceinline__ float lrelu(float v) { return v > 0.f ? v : 0.01f * v; }
__device__ __forceinline__ u64 pk2(float lo, float hi) {
    u64 r; asm("mov.b64 %0, {%1,%2};" : "=l"(r) : "f"(lo), "f"(hi)); return r;
}
__device__ __forceinline__ void upk2(u64 v, float& lo, float& hi) {
    asm("mov.b64 {%0,%1}, %2;" : "=f"(lo), "=f"(hi) : "l"(v));
}
__device__ __forceinline__ u64 ffma2(u64 a, u64 b, u64 c) {
    u64 d; asm("fma.rn.f32x2 %0,%1,%2,%3;" : "=l"(d) : "l"(a), "l"(b), "l"(c)); return d;
}

// shuffle-based block reductions (256 threads, 8 warps, 2 syncs each)
__device__ __forceinline__ float bredmax(float v, float* sh8) {
    int lane = threadIdx.x & 31, w = threadIdx.x >> 5;
#pragma unroll
    for (int o = 16; o; o >>= 1) v = fmaxf(v, __shfl_xor_sync(0xffffffffu, v, o));
    if (lane == 0) sh8[w] = v;
    __syncthreads();
    float m = fmaxf(fmaxf(fmaxf(sh8[0], sh8[1]), fmaxf(sh8[2], sh8[3])),
                    fmaxf(fmaxf(sh8[4], sh8[5]), fmaxf(sh8[6], sh8[7])));
    __syncthreads();
    return m;
}
__device__ __forceinline__ float bredsum(float v, float* sh8) {
    int lane = threadIdx.x & 31, w = threadIdx.x >> 5;
#pragma unroll
    for (int o = 16; o; o >>= 1) v += __shfl_xor_sync(0xffffffffu, v, o);
    if (lane == 0) sh8[w] = v;
    __syncthreads();
    float m = ((sh8[0] + sh8[1]) + (sh8[2] + sh8[3])) + ((sh8[4] + sh8[5]) + (sh8[6] + sh8[7]));
    __syncthreads();
    return m;
}

// ---------------- L1: histogram (2 edges/thread) ----------------
__global__ void k_hist(const int* __restrict__ ei) {
    int e = (blockIdx.x * 256 + threadIdx.x) * 2;
    int2 d2 = *(const int2*)&ei[EE + e];
    atomicAdd(&g_deg[d2.x], 1);
    atomicAdd(&g_deg[d2.y], 1);
}

// ---------------- L2: exclusive scan (warp-shuffle local scan + parallel lookback) ----------------
__global__ void k_scanF() {
    __shared__ int wsum[32];
    __shared__ int red[64];
    __shared__ int s_prev;
    int b = blockIdx.x, t = threadIdx.x;
    int w = t >> 5, l = t & 31;
    int i = b * 1024 + t;
    int v = g_deg[i];
    int s = v;
#pragma unroll
    for (int o = 1; o < 32; o <<= 1) {
        int n = __shfl_up_sync(0xffffffffu, s, o);
        if (l >= o) s += n;
    }
    if (l == 31) wsum[w] = s;
    __syncthreads();
    if (w == 0) {
        int t2 = wsum[l];
        int s2 = t2;
#pragma unroll
        for (int o = 1; o < 32; o <<= 1) {
            int n = __shfl_up_sync(0xffffffffu, s2, o);
            if (l >= o) s2 += n;
        }
        wsum[l] = s2;
    }
    __syncthreads();
    int incl = s + (w > 0 ? wsum[w - 1] : 0);
    int btotal = wsum[31];
    if (t == 0) {
        g_scanincl[b] = btotal;
        __threadfence();
        atomicExch(&g_scanflag[b], 1);
    }
    int pv = 0;
    if (t < b) {
        while (atomicAdd(&g_scanflag[t], 0) == 0) {}
        __threadfence();
        pv = g_scanincl[t];
    }
    if (t < 64) red[t] = pv;
    __syncthreads();
    if (t == 0) {
        int a = 0;
#pragma unroll
        for (int k = 0; k < 64; k++) a += red[k];
        s_prev = a;
    }
    __syncthreads();
    int off = incl - v + s_prev;
    g_off[i] = off;
    g_pos[i] = off;
    if (i == 0) g_off[NN] = EE;
}

// ---------------- L3: scatter to CSR (4 edges/thread, 4 independent chains) ----------------
__global__ void k_scatter(const int* __restrict__ ei) {
    int e = (blockIdx.x * 256 + threadIdx.x) * 4;
    int4 s4 = *(const int4*)&ei[e];
    int4 d4 = *(const int4*)&ei[EE + e];
    int p0 = atomicAdd(&g_pos[d4.x], 1);
    int p1 = atomicAdd(&g_pos[d4.y], 1);
    int p2 = atomicAdd(&g_pos[d4.z], 1);
    int p3 = atomicAdd(&g_pos[d4.w], 1);
    g_csr[p0] = s4.x;
    g_csr[p1] = s4.y;
    g_csr[p2] = s4.z;
    g_csr[p3] = s4.w;
}

// ---------------- L4 (ncu slot): FUSED max-agg + conv0 GEMM (byte-identical control) ----------------
__global__ void __launch_bounds__(256) k_conv0F(const float* __restrict__ x,
                                                const float* __restrict__ Wrel,
                                                const float* __restrict__ Wroot,
                                                const float* __restrict__ b0) {
    __shared__ __align__(16) char arena[43008];
    float (*aggS)[64] = reinterpret_cast<float(*)[64]>(arena);
    float (*s_red)[132] = reinterpret_cast<float(*)[132]>(arena);   // aliases aggS (epilogue)
    float (*inT)[76] = reinterpret_cast<float(*)[76]>(arena + 16384);
    float (*Ws)[132] = reinterpret_cast<float(*)[132]>(arena + 26112);

    int tid = threadIdx.x;
    int warp = tid >> 5, lane = tid & 31;
    int rbase = blockIdx.x * 64;

#pragma unroll
    for (int j = 0; j < 8; j++) {
        int node = warp * 8 + j;
        int row = rbase + node;
        int beg = g_off[row], end = g_off[row + 1];
        float2 m = make_float2(-INFINITY, -INFINITY);
        int e = beg;
        for (; e + 4 <= end; e += 4) {
            int s0 = g_csr[e], s1 = g_csr[e + 1], s2 = g_csr[e + 2], s3 = g_csr[e + 3];
            float2 v0 = *(const float2*)&x[s0 * FEAT + lane * 2];
            float2 v1 = *(const float2*)&x[s1 * FEAT + lane * 2];
            float2 v2 = *(const float2*)&x[s2 * FEAT + lane * 2];
            float2 v3 = *(const float2*)&x[s3 * FEAT + lane * 2];
            m.x = fmaxf(fmaxf(m.x, v0.x), fmaxf(fmaxf(v1.x, v2.x), v3.x));
            m.y = fmaxf(fmaxf(m.y, v0.y), fmaxf(fmaxf(v1.y, v2.y), v3.y));
        }
        for (; e < end; e++) {
            int s = g_csr[e];
            float2 v = *(const float2*)&x[s * FEAT + lane * 2];
            m.x = fmaxf(m.x, v.x);
            m.y = fmaxf(m.y, v.y);
        }
        if (beg == end) { m.x = 0.f; m.y = 0.f; }
        *(float2*)&aggS[node][lane * 2] = m;
    }
    __syncthreads();

    int tx = tid & 15, ty = tid >> 4;
    u64 acc2[4][4];
#pragma unroll
    for (int j = 0; j < 4; j++)
#pragma unroll
        for (int c = 0; c < 4; c++) acc2[j][c] = 0ull;

    for (int k0 = 0; k0 < 128; k0 += 32) {
        for (int idx = tid; idx < 32 * 64; idx += 256) {
            int r = idx >> 5, kk = idx & 31;
            int kg = k0 + kk;
            float v = (kg < 64) ? aggS[r][kg] : x[(rbase + r) * FEAT + (kg - 64)];
            inT[kk][r] = v;
        }
        for (int idx = tid; idx < 32 * 128; idx += 256) {
            int o = idx >> 5, kk = idx & 31;
            int kg = k0 + kk;
            float v = (kg < 64) ? Wrel[o * 64 + kg] : Wroot[o * 64 + (kg - 64)];
            Ws[kk][o] = v;
        }
        __syncthreads();
#pragma unroll
        for (int kk = 0; kk < 32; kk++) {
            float4 av4 = *(const float4*)&inT[kk][tx * 4];
            ulonglong2 wA = *(const ulonglong2*)&Ws[kk][ty * 8];
            ulonglong2 wB = *(const ulonglong2*)&Ws[kk][ty * 8 + 4];
            u64 w0 = wA.x, w1 = wA.y, w2 = wB.x, w3 = wB.y;
            u64 a0 = pk2(av4.x, av4.x), a1 = pk2(av4.y, av4.y);
            u64 a2 = pk2(av4.z, av4.z), a3 = pk2(av4.w, av4.w);
            acc2[0][0] = ffma2(a0, w0, acc2[0][0]);
            acc2[0][1] = ffma2(a0, w1, acc2[0][1]);
            acc2[0][2] = ffma2(a0, w2, acc2[0][2]);
            acc2[0][3] = ffma2(a0, w3, acc2[0][3]);
            acc2[1][0] = ffma2(a1, w0, acc2[1][0]);
            acc2[1][1] = ffma2(a1, w1, acc2[1][1]);
            acc2[1][2] = ffma2(a1, w2, acc2[1][2]);
            acc2[1][3] = ffma2(a1, w3, acc2[1][3]);
            acc2[2][0] = ffma2(a2, w0, acc2[2][0]);
            acc2[2][1] = ffma2(a2, w1, acc2[2][1]);
            acc2[2][2] = ffma2(a2, w2, acc2[2][2]);
            acc2[2][3] = ffma2(a2, w3, acc2[2][3]);
            acc2[3][0] = ffma2(a3, w0, acc2[3][0]);
            acc2[3][1] = ffma2(a3, w1, acc2[3][1]);
            acc2[3][2] = ffma2(a3, w2, acc2[3][2]);
            acc2[3][3] = ffma2(a3, w3, acc2[3][3]);
        }
        __syncthreads();
    }

    float vals[4][8];
#pragma unroll
    for (int j = 0; j < 4; j++) {
        int row = rbase + tx * 4 + j;
        float2* orow = (float2*)&g_cur[(size_t)row * EMB + ty * 8];
#pragma unroll
        for (int c = 0; c < 4; c++) {
            float lo, hi;
            upk2(acc2[j][c], lo, hi);
            int col = ty * 8 + c * 2;
            float v0 = lrelu(lo + b0[col]);
            float v1 = lrelu(hi + b0[col + 1]);
            vals[j][c * 2] = v0; vals[j][c * 2 + 1] = v1;
            orow[c] = make_float2(v0, v1);
        }
    }
    float psum[8], pssq[8];
#pragma unroll
    for (int c = 0; c < 8; c++) {
        float s = 0.f, q = 0.f;
#pragma unroll
        for (int j = 0; j < 4; j++) { s += vals[j][c]; q += vals[j][c] * vals[j][c]; }
        psum[c] = s; pssq[c] = q;
    }
    __syncthreads();
#pragma unroll
    for (int c = 0; c < 8; c++) s_red[tx][ty * 8 + c] = psum[c];
    __syncthreads();
    if (tid < 128) {
        float s = 0.f;
#pragma unroll
        for (int k = 0; k < 16; k++) s += s_red[k][tid];
        atomicAdd(&g_bsum[tid], s);
    }
    __syncthreads();
#pragma unroll
    for (int c = 0; c < 8; c++) s_red[tx][ty * 8 + c] = pssq[c];
    __syncthreads();
    if (tid < 128) {
        float s = 0.f;
#pragma unroll
        for (int k = 0; k < 16; k++) s += s_red[k][tid];
        atomicAdd(&g_bsumsq[tid], s);
    }
}

// ---------------- fused BN-apply (or residual-update) + 4-head scores (2 rows/warp) ----------------
__global__ void __launch_bounds__(256) k_norm_scores(const float* __restrict__ gg,
                                                     const float* __restrict__ bb,
                                                     const float* __restrict__ w4,
                                                     int mode) {
    __shared__ float ws[512];
    int tid = threadIdx.x;
    ws[tid] = w4[tid];
    ws[tid + 256] = w4[tid + 256];
    if (blockIdx.x == 0 && tid < NHD) g_kcnt[tid] = 0;
    __syncthreads();
    int w = tid >> 5, l = tid & 31;
    int row0 = blockIdx.x * 16 + w * 2;
    int f = l * 4;
    const float inv = 1.0f / 65536.0f;
    float4 cg = *(const float4*)&gg[f];
    float4 cb = *(const float4*)&bb[f];
    float4 s4 = *(const float4*)&g_bsum[f];
    float4 q4 = *(const float4*)&g_bsumsq[f];
    float mu0 = s4.x * inv, mu1 = s4.y * inv, mu2 = s4.z * inv, mu3 = s4.w * inv;
    float r0 = rsqrtf(q4.x * inv - mu0 * mu0 + 1e-5f);
    float r1 = rsqrtf(q4.y * inv - mu1 * mu1 + 1e-5f);
    float r2 = rsqrtf(q4.z * inv - mu2 * mu2 + 1e-5f);
    float r3 = rsqrtf(q4.w * inv - mu3 * mu3 + 1e-5f);
    float outv[2][4];
#pragma unroll
    for (int r = 0; r < 2; r++) {
        int row = row0 + r;
        float4 cv = *(const float4*)&g_cur[(size_t)row * EMB + f];
        float v0, v1, v2, v3;
        if (mode == 0) {
            v0 = cg.x * (cv.x - mu0) * r0 + cb.x;
            v1 = cg.y * (cv.y - mu1) * r1 + cb.y;
            v2 = cg.z * (cv.z - mu2) * r2 + cb.z;
            v3 = cg.w * (cv.w - mu3) * r3 + cb.w;
        } else {
            float4 nv = make_float4(0.f, 0.f, 0.f, 0.f);
            unsigned km = g_keepm[row];
            if ((km >> (l >> 3)) & 1u) nv = *(const float4*)&g_new[(size_t)row * EMB + f];
            float b0v = cg.x * (nv.x - mu0) * r0 + cb.x;
            float b1v = cg.y * (nv.y - mu1) * r1 + cb.y;
            float b2v = cg.z * (nv.z - mu2) * r2 + cb.z;
            float b3v = cg.w * (nv.w - mu3) * r3 + cb.w;
            v0 = 0.5f * (cv.x + 0.5f * b0v);
            v1 = 0.5f * (cv.y + 0.5f * b1v);
            v2 = 0.5f * (cv.z + 0.5f * b2v);
            v3 = 0.5f * (cv.w + 0.5f * b3v);
        }
        *(float4*)&g_cur[(size_t)row * EMB + f] = make_float4(v0, v1, v2, v3);
        outv[r][0] = v0; outv[r][1] = v1; outv[r][2] = v2; outv[r][3] = v3;
    }
    float p[2][NHD];
#pragma unroll
    for (int r = 0; r < 2; r++)
#pragma unroll
        for (int h = 0; h < NHD; h++) {
            const float* wh = &ws[h * EMB + f];
            p[r][h] = outv[r][0] * wh[0] + outv[r][1] * wh[1] +
                      outv[r][2] * wh[2] + outv[r][3] * wh[3];
        }
#pragma unroll
    for (int o = 16; o; o >>= 1) {
#pragma unroll
        for (int r = 0; r < 2; r++)
#pragma unroll
            for (int h = 0; h < NHD; h++)
                p[r][h] += __shfl_down_sync(0xffffffffu, p[r][h], o);
    }
    if (l == 0) {
#pragma unroll
        for (int r = 0; r < 2; r++)
#pragma unroll
            for (int h = 0; h < NHD; h++)
                g_scores[h * NN + row0 + r] = p[r][h];
    }
}

// ---------------- topk pool: 4 heads' reductions interleaved (2 syncs total) ----------------
__global__ void k_poolkeep(float minscore) {
    __shared__ float shm[NHD][8];
    __shared__ float shs[NHD][8];
    int t = threadIdx.x;
    int lane = t & 31, w = t >> 5;
    int i = blockIdx.x * GSZ + t;
    if (blockIdx.x == 0 && t < 128) { g_bsum[t] = 0.f; g_bsumsq[t] = 0.f; }

    float sc[NHD];
#pragma unroll
    for (int h = 0; h < NHD; h++) sc[h] = g_scores[h * NN + i];

    // 4 concurrent max butterflies
    float mx[NHD];
#pragma unroll
    for (int h = 0; h < NHD; h++) mx[h] = sc[h];
#pragma unroll
    for (int o = 16; o; o >>= 1)
#pragma unroll
        for (int h = 0; h < NHD; h++)
            mx[h] = fmaxf(mx[h], __shfl_xor_sync(0xffffffffu, mx[h], o));
    if (lane == 0)
#pragma unroll
        for (int h = 0; h < NHD; h++) shm[h][w] = mx[h];
    __syncthreads();
    float m[NHD], ex[NHD];
#pragma unroll
    for (int h = 0; h < NHD; h++) {
        m[h] = fmaxf(fmaxf(fmaxf(shm[h][0], shm[h][1]), fmaxf(shm[h][2], shm[h][3])),
                     fmaxf(fmaxf(shm[h][4], shm[h][5]), fmaxf(shm[h][6], shm[h][7])));
        ex[h] = expf(sc[h] - m[h]);
    }
    // 4 concurrent sum butterflies
    float sm_[NHD];
#pragma unroll
    for (int h = 0; h < NHD; h++) sm_[h] = ex[h];
#pragma unroll
    for (int o = 16; o; o >>= 1)
#pragma unroll
        for (int h = 0; h < NHD; h++)
            sm_[h] += __shfl_xor_sync(0xffffffffu, sm_[h], o);
    if (lane == 0)
#pragma unroll
        for (int h = 0; h < NHD; h++) shs[h][w] = sm_[h];
    __syncthreads();
    unsigned mask = 0;
#pragma unroll
    for (int h = 0; h < NHD; h++) {
        float sum = ((shs[h][0] + shs[h][1]) + (shs[h][2] + shs[h][3])) +
                    ((shs[h][4] + shs[h][5]) + (shs[h][6] + shs[h][7]));
        float sm = ex[h] / (sum + 1e-16f);
        float smax = 1.0f / (sum + 1e-16f);
        float thr = fminf(smax - 1e-7f, minscore);
        g_smv[h * NN + i] = sm;
        if (sm > thr) {
            mask |= 1u << h;
            int p = atomicAdd(&g_kcnt[h], 1);
            g_klist[h * NN + p] = i;
        }
    }
    g_keepm[i] = (unsigned char)mask;
}

// ---------------- per-head GraphConv on kept nodes: CSR-walk aggregation + GEMM ----------------
__global__ void k_headgemm(int bi, const float* __restrict__ Wrel,
                           const float* __restrict__ Wroot, const float* __restrict__ bias) {
    int h = blockIdx.y;
    int cnt = g_kcnt[h];
    __shared__ float As[EMB], xs[EMB], pr[128];
    const float* Wr = Wrel + (size_t)((bi * NHD + h) * OUTD) * EMB;
    const float* Wo = Wroot + (size_t)((bi * NHD + h) * OUTD) * EMB;
    const float* bb = bias + (bi * NHD + h) * OUTD;
    int t = threadIdx.x;
    for (int idx = blockIdx.x; idx < cnt; idx += gridDim.x) {
        int i = g_klist[h * NN + idx];
        float smi = g_smv[h * NN + i];
        int beg = g_off[i], end = g_off[i + 1];
        float m = -INFINITY;
        bool any = false;
        for (int e = beg; e < end; e++) {
            int s = g_csr[e];
            if ((g_keepm[s] >> h) & 1u) {
                any = true;
                float smv = g_smv[h * NN + s];
                m = fmaxf(m, g_cur[(size_t)s * EMB + t] * smv);
            }
        }
        As[t] = any ? m : 0.f;
        xs[t] = g_cur[(size_t)i * EMB + t] * smi;
        __syncthreads();
        int c = t & 31, q = t >> 5;
        float acc = 0.f;
#pragma unroll 8
        for (int k = q * 32; k < q * 32 + 32; k++)
            acc += As[k] * Wr[c * EMB + k] + xs[k] * Wo[c * EMB + k];
        pr[t] = acc;
        __syncthreads();
        if (t < 32) {
            float o = pr[t] + pr[t + 32] + pr[t + 64] + pr[t + 96] + bb[t];
            o = lrelu(o);
            g_new[(size_t)i * EMB + h * OUTD + t] = o;
            atomicAdd(&g_bsum[h * OUTD + t], o);
            atomicAdd(&g_bsumsq[h * OUTD + t], o * o);
        }
        __syncthreads();
    }
}

// ---------------- classification heads + fused log_softmax + end-of-run re-zeroing ----------------
__global__ void k_cls(const float* __restrict__ gW1, const float* __restrict__ gb1,
                      const float* __restrict__ gW2, const float* __restrict__ gb2,
                      const float* __restrict__ fW1, const float* __restrict__ fb1,
                      const float* __restrict__ fW2, const float* __restrict__ fb2,
                      float* __restrict__ out) {
    __shared__ float sh8[8];
    __shared__ float sms[256], xsh[EMB], gates[256], pooled[EMB], part[128];
    __shared__ int list[256];
    __shared__ int cnt;
    __shared__ int s_old;
    int g = blockIdx.x, c = blockIdx.y, t = threadIdx.x;
    if (c == 0) g_deg[g * 256 + t] = 0;
    if (g == 0 && c == 0) {
        if (t < 64) g_scanflag[t] = 0;
        if (t < 128) { g_bsum[t] = 0.f; g_bsumsq[t] = 0.f; }
    }
    int i = g * GSZ + t;
    float s = g_scores[c * NN + i];
    float m = bredmax(s, sh8);
    float e = expf(s - m);
    float sum = bredsum(e, sh8);
    float sm = e / (sum + 1e-16f);
    sms[t] = sm;
    float smax = 1.0f / (sum + 1e-16f);
    float thr = fminf(smax - 1e-7f, 0.8f);
    bool keep = sm > thr;
    if (t == 0) cnt = 0;
    __syncthreads();
    if (keep) { int p = atomicAdd(&cnt, 1); list[p] = t; }
    __syncthreads();
    int C = cnt;

    for (int idx = 0; idx < C; idx++) {
        int tt = list[idx];
        int ii = g * GSZ + tt;
        if (t < 128) xsh[t] = g_cur[(size_t)ii * EMB + t] * sms[tt];
        __syncthreads();
        if (t < 128) {
            const float* w = gW1 + ((size_t)c * EMB + t) * EMB;
            float u = gb1[c * EMB + t];
#pragma unroll 8
            for (int k = 0; k < EMB; k++) u += xsh[k] * w[k];
            u = lrelu(u);
            part[t] = u * gW2[c * EMB + t];
        }
        __syncthreads();
        if (t < 64) part[t] += part[t + 64];
        __syncthreads();
        if (t < 32) {
            float v = part[t] + part[t + 32];
#pragma unroll
            for (int o = 16; o; o >>= 1) v += __shfl_down_sync(0xffffffffu, v, o);
            if (t == 0) gates[idx] = v + gb2[c];
        }
        __syncthreads();
    }

    float gv = (t < C) ? gates[t] : -INFINITY;
    float m2 = bredmax(gv, sh8);
    float e2 = (t < C) ? expf(gv - m2) : 0.f;
    float s2 = bredsum(e2, sh8);
    float a = e2 / (s2 + 1e-16f);
    __syncthreads();
    if (t < C) gates[t] = a;
    __syncthreads();

    if (t < 128) {
        float acc = 0.f;
        for (int idx = 0; idx < C; idx++) {
            int tt = list[idx];
            acc += gates[idx] * g_cur[(size_t)(g * GSZ + tt) * EMB + t] * sms[tt];
        }
        pooled[t] = acc;
    }
    __syncthreads();

    if (t < 128) {
        const float* w = fW1 + ((size_t)c * EMB + t) * EMB;
        float u = fb1[c * EMB + t];
#pragma unroll 8
        for (int k = 0; k < EMB; k++) u += pooled[k] * w[k];
        u = lrelu(u);
        part[t] = u * fW2[c * EMB + t];
    }
    __syncthreads();
    if (t < 64) part[t] += part[t + 64];
    __syncthreads();
    if (t < 32) {
        float v = part[t] + part[t + 32];
#pragma unroll
        for (int o = 16; o; o >>= 1) v += __shfl_down_sync(0xffffffffu, v, o);
        if (t == 0) {
            g_logits[g * NCL + c] = v + fb2[c];
            __threadfence();
            s_old = atomicAdd(&g_done[g], 1);
        }
    }
    __syncthreads();
    // last-finishing class block computes this graph's log_softmax (self-resetting counter)
    if (s_old == NCL - 1 && t == 0) {
        __threadfence();
        float l0 = g_logits[g * NCL + 0], l1 = g_logits[g * NCL + 1];
        float l2 = g_logits[g * NCL + 2], l3 = g_logits[g * NCL + 3];
        float mm = fmaxf(fmaxf(l0, l1), fmaxf(l2, l3));
        float ss = expf(l0 - mm) + expf(l1 - mm) + expf(l2 - mm) + expf(l3 - mm);
        float ls = logf(ss);
        out[g * NCL + 0] = l0 - mm - ls;
        out[g * NCL + 1] = l1 - mm - ls;
        out[g * NCL + 2] = l2 - mm - ls;
        out[g * NCL + 3] = l3 - mm - ls;
        g_done[g] = 0;   // reset for next replay
    }
}

// ---------------- launch ----------------
extern "C" void kernel_launch(void* const* d_in, const int* in_sizes, int n_in,
                              void* d_out, int out_size) {
    const float* x = (const float*)d_in[0];
    const int* ei = (const int*)d_in[1];
    const float* W_rel0 = (const float*)d_in[3];
    const float* W_root0 = (const float*)d_in[4];
    const float* b0 = (const float*)d_in[5];
    const float* bn0_g = (const float*)d_in[6];
    const float* bn0_b = (const float*)d_in[7];
    const float* blk_pool_w = (const float*)d_in[8];
    const float* blk_Wrel = (const float*)d_in[9];
    const float* blk_Wroot = (const float*)d_in[10];
    const float* blk_b = (const float*)d_in[11];
    const float* blk_bn_g = (const float*)d_in[12];
    const float* blk_bn_b = (const float*)d_in[13];
    const float* cls_pool_w = (const float*)d_in[14];
    const float* cls_gW1 = (const float*)d_in[15];
    const float* cls_gb1 = (const float*)d_in[16];
    const float* cls_gW2 = (const float*)d_in[17];
    const float* cls_gb2 = (const float*)d_in[18];
    const float* cls_fW1 = (const float*)d_in[19];
    const float* cls_fb1 = (const float*)d_in[20];
    const float* cls_fW2 = (const float*)d_in[21];
    const float* cls_fb2 = (const float*)d_in[22];
    float* out = (float*)d_out;

    k_hist<<<EE / 512, 256>>>(ei);              // 1
    k_scanF<<<64, 1024>>>();                    // 2
    k_scatter<<<EE / 1024, 256>>>(ei);          // 3
    k_conv0F<<<NN / 64, 256>>>(x, W_rel0, W_root0, b0);                   // 4 <- ncu slot
    k_norm_scores<<<NN / 16, 256>>>(bn0_g, bn0_b, blk_pool_w, 0);         // 5

    for (int bi = 0; bi < NBLK; bi++) {
        k_poolkeep<<<GB, 256>>>(0.7f);
        k_headgemm<<<dim3(256, NHD), 128>>>(bi, blk_Wrel, blk_Wroot, blk_b);
        const float* nxt = (bi == 0) ? (blk_pool_w + (size_t)NHD * EMB) : cls_pool_w;
        k_norm_scores<<<NN / 16, 256>>>(blk_bn_g + bi * EMB, blk_bn_b + bi * EMB, nxt, 1);
    }

    k_cls<<<dim3(GB, NCL), 256>>>(cls_gW1, cls_gb1, cls_gW2, cls_gb2,
                                  cls_fW1, cls_fb1, cls_fW2, cls_fb2, out);
}